// round 1
// baseline (speedup 1.0000x reference)
#include <cuda_runtime.h>
#include <cstdint>
#include <cstddef>

#define LR_C   0.001f
#define TAU_C  1000.0f

#define BMt 128
#define BNt 128
#define BKt 8
#define RSPLIT 64

// Scratch for column-sum partials (alloc-free rule: __device__ global).
__device__ float g_partial[RSPLIT * 4096];

// ---------------------------------------------------------------------------
// GEMM1: C[M,N] = A[M,K] * B[N,K]^T   (both operands K-major / row-major)
// 128x128 tile, BK=8, 256 threads, 8x8 per thread with 4+4 split mapping.
// ---------------------------------------------------------------------------
__global__ __launch_bounds__(256) void gemm_nt_kernel(
    const float* __restrict__ A, const float* __restrict__ Bm,
    float* __restrict__ C, int M, int N, int K)
{
    __shared__ float As[BKt][BMt];
    __shared__ float Bs[BKt][BNt];

    const int tid = threadIdx.x;
    const int tx = tid & 15;      // 0..15 -> N
    const int ty = tid >> 4;      // 0..15 -> M
    const int lrow = tid >> 1;    // 0..127
    const int lcol = (tid & 1) * 4;

    const float* Ab = A + (size_t)blockIdx.y * BMt * K;
    const float* Bb = Bm + (size_t)blockIdx.x * BNt * K;

    float acc[8][8];
    #pragma unroll
    for (int i = 0; i < 8; i++)
        #pragma unroll
        for (int j = 0; j < 8; j++) acc[i][j] = 0.f;

    for (int k0 = 0; k0 < K; k0 += BKt) {
        float4 av = *(const float4*)(Ab + (size_t)lrow * K + k0 + lcol);
        float4 bv = *(const float4*)(Bb + (size_t)lrow * K + k0 + lcol);
        __syncthreads();
        As[lcol+0][lrow] = av.x; As[lcol+1][lrow] = av.y;
        As[lcol+2][lrow] = av.z; As[lcol+3][lrow] = av.w;
        Bs[lcol+0][lrow] = bv.x; Bs[lcol+1][lrow] = bv.y;
        Bs[lcol+2][lrow] = bv.z; Bs[lcol+3][lrow] = bv.w;
        __syncthreads();

        #pragma unroll
        for (int kk = 0; kk < BKt; kk++) {
            float a[8], b[8];
            #pragma unroll
            for (int i = 0; i < 4; i++) {
                a[i]     = As[kk][ty*4 + i];
                a[4 + i] = As[kk][64 + ty*4 + i];
            }
            #pragma unroll
            for (int j = 0; j < 4; j++) {
                b[j]     = Bs[kk][tx*4 + j];
                b[4 + j] = Bs[kk][64 + tx*4 + j];
            }
            #pragma unroll
            for (int i = 0; i < 8; i++)
                #pragma unroll
                for (int j = 0; j < 8; j++)
                    acc[i][j] = fmaf(a[i], b[j], acc[i][j]);
        }
    }

    const int mbase = blockIdx.y * BMt;
    const int nbase = blockIdx.x * BNt;
    #pragma unroll
    for (int ih = 0; ih < 2; ih++) {
        #pragma unroll
        for (int ii = 0; ii < 4; ii++) {
            int i = ih * 4 + ii;
            int m = mbase + ih * 64 + ty * 4 + ii;
            float4 v0 = make_float4(acc[i][0], acc[i][1], acc[i][2], acc[i][3]);
            float4 v1 = make_float4(acc[i][4], acc[i][5], acc[i][6], acc[i][7]);
            *(float4*)(C + (size_t)m * N + nbase + tx*4)      = v0;
            *(float4*)(C + (size_t)m * N + nbase + 64 + tx*4) = v1;
        }
    }
}

// ---------------------------------------------------------------------------
// Column partial sums of output (B x OUT). Grid: (OUT/256, RSPLIT).
// ---------------------------------------------------------------------------
__global__ void colsum_kernel(const float* __restrict__ Out, int Bn, int OUTn)
{
    int col = blockIdx.x * blockDim.x + threadIdx.x;
    if (col >= OUTn) return;
    int rows_per = Bn / RSPLIT;
    int r0 = blockIdx.y * rows_per;
    float s = 0.f;
    for (int r = 0; r < rows_per; r++)
        s += Out[(size_t)(r0 + r) * OUTn + col];
    g_partial[blockIdx.y * OUTn + col] = s;
}

// new_threshold = th + (mean(out,axis=0)^2 - th) / TAU
__global__ void thresh_kernel(const float* __restrict__ th_old,
                              float* __restrict__ th_new, int Bn, int OUTn)
{
    int c = blockIdx.x * blockDim.x + threadIdx.x;
    if (c >= OUTn) return;
    float s = 0.f;
    #pragma unroll 8
    for (int p = 0; p < RSPLIT; p++) s += g_partial[p * OUTn + c];
    float act = s / (float)Bn;
    float t = th_old[c];
    th_new[c] = t + (act * act - t) / TAU_C;
}

// ---------------------------------------------------------------------------
// GEMM2 (Hebbian): Wnew[o,i] = Wold[o,i] + scale * sum_b relu(Out[b,o]-th[o]) * X[b,i]
// A-tile = post (relu applied on load), reduction dim = b (rows of Out/X).
// ---------------------------------------------------------------------------
__global__ __launch_bounds__(256) void gemm_hebb_kernel(
    const float* __restrict__ Out,   // B x OUT
    const float* __restrict__ X,     // B x IN
    const float* __restrict__ Wold,  // OUT x IN
    const float* __restrict__ thn,   // OUT (new threshold)
    float* __restrict__ Wnew,        // OUT x IN
    int Bn, int OUTn, int INn, float scale)
{
    __shared__ float As[BKt][BMt];   // post tile [b][o]
    __shared__ float Bs[BKt][BNt];   // x tile    [b][i]
    __shared__ float th_s[BMt];

    const int tid = threadIdx.x;
    const int tx = tid & 15;         // -> IN
    const int ty = tid >> 4;         // -> OUT
    const int obase = blockIdx.y * BMt;
    const int ibase = blockIdx.x * BNt;

    if (tid < BMt) th_s[tid] = thn[obase + tid];
    __syncthreads();

    const int lb  = tid >> 5;        // 0..7  (b within K-tile)
    const int lo4 = (tid & 31) * 4;  // 0..124

    float acc[8][8];
    #pragma unroll
    for (int i = 0; i < 8; i++)
        #pragma unroll
        for (int j = 0; j < 8; j++) acc[i][j] = 0.f;

    for (int b0 = 0; b0 < Bn; b0 += BKt) {
        float4 ov = *(const float4*)(Out + (size_t)(b0 + lb) * OUTn + obase + lo4);
        float4 xv = *(const float4*)(X   + (size_t)(b0 + lb) * INn  + ibase + lo4);
        __syncthreads();
        As[lb][lo4+0] = fmaxf(ov.x - th_s[lo4+0], 0.f);
        As[lb][lo4+1] = fmaxf(ov.y - th_s[lo4+1], 0.f);
        As[lb][lo4+2] = fmaxf(ov.z - th_s[lo4+2], 0.f);
        As[lb][lo4+3] = fmaxf(ov.w - th_s[lo4+3], 0.f);
        Bs[lb][lo4+0] = xv.x; Bs[lb][lo4+1] = xv.y;
        Bs[lb][lo4+2] = xv.z; Bs[lb][lo4+3] = xv.w;
        __syncthreads();

        #pragma unroll
        for (int kk = 0; kk < BKt; kk++) {
            float a[8], b[8];
            #pragma unroll
            for (int i = 0; i < 4; i++) {
                a[i]     = As[kk][ty*4 + i];
                a[4 + i] = As[kk][64 + ty*4 + i];
            }
            #pragma unroll
            for (int j = 0; j < 4; j++) {
                b[j]     = Bs[kk][tx*4 + j];
                b[4 + j] = Bs[kk][64 + tx*4 + j];
            }
            #pragma unroll
            for (int i = 0; i < 8; i++)
                #pragma unroll
                for (int j = 0; j < 8; j++)
                    acc[i][j] = fmaf(a[i], b[j], acc[i][j]);
        }
    }

    #pragma unroll
    for (int ih = 0; ih < 2; ih++) {
        #pragma unroll
        for (int ii = 0; ii < 4; ii++) {
            int i = ih * 4 + ii;
            int o = obase + ih * 64 + ty * 4 + ii;
            size_t base = (size_t)o * INn + ibase;
            float4 w0 = *(const float4*)(Wold + base + tx*4);
            float4 w1 = *(const float4*)(Wold + base + 64 + tx*4);
            w0.x += scale * acc[i][0]; w0.y += scale * acc[i][1];
            w0.z += scale * acc[i][2]; w0.w += scale * acc[i][3];
            w1.x += scale * acc[i][4]; w1.y += scale * acc[i][5];
            w1.z += scale * acc[i][6]; w1.w += scale * acc[i][7];
            *(float4*)(Wnew + base + tx*4)      = w0;
            *(float4*)(Wnew + base + 64 + tx*4) = w1;
        }
    }
}

// ---------------------------------------------------------------------------
extern "C" void kernel_launch(void* const* d_in, const int* in_sizes, int n_in,
                              void* d_out, int out_size)
{
    const float* x  = (const float*)d_in[0];
    const float* w  = (const float*)d_in[1];
    const float* th = (const float*)d_in[2];

    const int OUT = in_sizes[2];              // 4096
    const int IN  = in_sizes[1] / OUT;        // 4096
    const int Bn  = in_sizes[0] / IN;         // 8192

    float* out    = (float*)d_out;
    float* out_O  = out;                          // B x OUT
    float* out_th = out + (size_t)Bn * OUT;       // OUT
    float* out_W  = out_th + OUT;                 // OUT x IN

    // 1) output = x @ W^T
    dim3 g1(OUT / BNt, Bn / BMt);
    gemm_nt_kernel<<<g1, 256>>>(x, w, out_O, Bn, OUT, IN);

    // 2) threshold EMA (deterministic 2-stage column reduction)
    dim3 gr((OUT + 255) / 256, RSPLIT);
    colsum_kernel<<<gr, 256>>>(out_O, Bn, OUT);
    thresh_kernel<<<(OUT + 255) / 256, 256>>>(th, out_th, Bn, OUT);

    // 3) Wnew = W + (LR/B) * relu(output - th_new)^T @ x
    dim3 g2(IN / BNt, OUT / BMt);
    gemm_hebb_kernel<<<g2, 256>>>(out_O, x, w, out_th, out_W,
                                  Bn, OUT, IN, LR_C / (float)Bn);
}

// round 3
// speedup vs baseline: 4.0139x; 4.0139x over previous
#include <cuda_runtime.h>
#include <cstdint>
#include <cstddef>

#define LR_C   0.001f
#define TAU_C  1000.0f

// GEMM tiling
#define BM 128
#define BN 128
#define BKT 32
#define NSTAGES 3
#define STAGE_BYTES (2 * BM * 128)          // As 16KB + Bs 16KB
#define SMEM_TOTAL (NSTAGES * STAGE_BYTES)  // 96 KB
#define RSPLIT 64

// Fixed problem shape: B=8192, IN=OUT=4096.
#define DIM_B   8192
#define DIM_IO  4096

// Scratch (__device__ globals: the sanctioned alloc-free workaround)
__device__ float g_xr[(size_t)DIM_B * DIM_IO];   // rna(x)            B x IN
__device__ float g_wr[(size_t)DIM_IO * DIM_IO];  // rna(w)            OUT x IN
__device__ float g_xt[(size_t)DIM_IO * DIM_B];   // rna(x)^T          IN x B
__device__ float g_pt[(size_t)DIM_IO * DIM_B];   // rna(relu(o-th))^T OUT x B
__device__ float g_partial[RSPLIT * DIM_IO];

// ---------------------------------------------------------------------------
// PTX helpers (baseline sm_80+ features ONLY — no tcgen05 on this toolchain)
// ---------------------------------------------------------------------------
__device__ __forceinline__ uint32_t smem_u32(const void* p) {
    return (uint32_t)__cvta_generic_to_shared(p);
}

__device__ __forceinline__ float rna_tf32(float x) {
    uint32_t r;
    asm("cvt.rna.tf32.f32 %0, %1;" : "=r"(r) : "f"(x));
    return __uint_as_float(r);
}

__device__ __forceinline__ void cp_async16(uint32_t s, const void* g) {
    asm volatile("cp.async.cg.shared.global [%0], [%1], 16;\n" :: "r"(s), "l"(g));
}
#define CP_COMMIT() asm volatile("cp.async.commit_group;\n" ::)
#define CP_WAIT1()  asm volatile("cp.async.wait_group 1;\n" ::: "memory")

__device__ __forceinline__ float lds_f(uint32_t addr) {
    float v;
    asm volatile("ld.shared.f32 %0, [%1];" : "=f"(v) : "r"(addr));
    return v;
}

__device__ __forceinline__ uint32_t sw128(uint32_t off) {
    return off ^ ((off >> 3) & 0x70);
}

// m16n8k8 tf32 MMA (A row-major frag, B col-major frag), fp32 accumulate
__device__ __forceinline__ void mma_1688(float* c, const float* a, const float* b) {
    asm volatile(
        "mma.sync.aligned.m16n8k8.row.col.f32.tf32.tf32.f32 "
        "{%0,%1,%2,%3}, {%4,%5,%6,%7}, {%8,%9}, {%0,%1,%2,%3};"
        : "+f"(c[0]), "+f"(c[1]), "+f"(c[2]), "+f"(c[3])
        : "r"(__float_as_uint(a[0])), "r"(__float_as_uint(a[1])),
          "r"(__float_as_uint(a[2])), "r"(__float_as_uint(a[3])),
          "r"(__float_as_uint(b[0])), "r"(__float_as_uint(b[1])));
}

// ---------------------------------------------------------------------------
// TF32 tensor-core GEMM: C[M,N] = A[M,K] * B[N,K]^T (both row-major / K-major)
// mode 0: C = D       mode 1: C = Wold + scale * D
// ---------------------------------------------------------------------------
__device__ __forceinline__ void load_stage(uint32_t smem_base, int stage,
                                           const float* Ab, const float* Bb,
                                           int K, int k0, int tid) {
    uint32_t sa = smem_base + stage * STAGE_BYTES;
    uint32_t sb = sa + BM * 128;
    #pragma unroll
    for (int i = 0; i < 4; i++) {            // A: 128 rows x 8 x 16B chunks
        int idx = tid + i * 256;
        int row = idx >> 3, c = idx & 7;
        cp_async16(sa + sw128((uint32_t)(row * 128 + c * 16)),
                   (const char*)(Ab + (size_t)row * K + k0) + c * 16);
    }
    #pragma unroll
    for (int i = 0; i < 4; i++) {            // B: 128 rows x 8 x 16B chunks
        int idx = tid + i * 256;
        int row = idx >> 3, c = idx & 7;
        cp_async16(sb + sw128((uint32_t)(row * 128 + c * 16)),
                   (const char*)(Bb + (size_t)row * K + k0) + c * 16);
    }
}

__global__ __launch_bounds__(256, 2) void gemm_mma_kernel(
    const float* __restrict__ A, const float* __restrict__ Bmat,
    const float* __restrict__ Wold, float* __restrict__ C,
    int M, int N, int K, float scale, int mode)
{
    extern __shared__ char smem[];
    const uint32_t smem_base = smem_u32(smem);
    const int tid  = threadIdx.x;
    const int warp = tid >> 5, lane = tid & 31;
    const int wm = warp >> 2, wn = warp & 3;       // 2 x 4 warp grid
    const int lr = lane >> 2, lc = lane & 3;

    const int mbase = blockIdx.y * BM;
    const int nbase = blockIdx.x * BN;
    const float* Ab = A + (size_t)mbase * K;
    const float* Bb = Bmat + (size_t)nbase * K;

    float acc[4][4][4];                            // [mt][nt][frag]
    #pragma unroll
    for (int i = 0; i < 4; i++)
        #pragma unroll
        for (int j = 0; j < 4; j++)
            #pragma unroll
            for (int f = 0; f < 4; f++) acc[i][j][f] = 0.f;

    const int niter = K / BKT;

    load_stage(smem_base, 0, Ab, Bb, K, 0, tid);   CP_COMMIT();
    load_stage(smem_base, 1, Ab, Bb, K, BKT, tid); CP_COMMIT();

    int buf = 0;
    for (int it = 0; it < niter; ++it) {
        CP_WAIT1();
        __syncthreads();
        uint32_t sa = smem_base + buf * STAGE_BYTES;
        uint32_t sb = sa + BM * 128;

        #pragma unroll
        for (int ks = 0; ks < BKT / 8; ks++) {
            const int k0 = ks * 8;
            float a[4][4], b[4][2];
            #pragma unroll
            for (int mt = 0; mt < 4; mt++) {
                int r = wm * 64 + mt * 16 + lr;
                uint32_t c0 = (uint32_t)((k0 + lc) * 4);
                a[mt][0] = lds_f(sa + sw128((uint32_t)(r * 128) + c0));
                a[mt][1] = lds_f(sa + sw128((uint32_t)((r + 8) * 128) + c0));
                a[mt][2] = lds_f(sa + sw128((uint32_t)(r * 128) + c0 + 16));
                a[mt][3] = lds_f(sa + sw128((uint32_t)((r + 8) * 128) + c0 + 16));
            }
            #pragma unroll
            for (int nt = 0; nt < 4; nt++) {
                int n = wn * 32 + nt * 8 + lr;
                uint32_t c0 = (uint32_t)((k0 + lc) * 4);
                b[nt][0] = lds_f(sb + sw128((uint32_t)(n * 128) + c0));
                b[nt][1] = lds_f(sb + sw128((uint32_t)(n * 128) + c0 + 16));
            }
            #pragma unroll
            for (int mt = 0; mt < 4; mt++)
                #pragma unroll
                for (int nt = 0; nt < 4; nt++)
                    mma_1688(acc[mt][nt], a[mt], b[nt]);
        }

        const int itn = it + 2;
        if (itn < niter)
            load_stage(smem_base, itn % NSTAGES, Ab, Bb, K, itn * BKT, tid);
        CP_COMMIT();
        buf = (buf + 1 == NSTAGES) ? 0 : buf + 1;
    }

    // Epilogue: per thread 4x4 tiles, two float2 rows each
    #pragma unroll
    for (int mt = 0; mt < 4; mt++) {
        int r0 = mbase + wm * 64 + mt * 16 + lr;
        #pragma unroll
        for (int nt = 0; nt < 4; nt++) {
            int cc = nbase + wn * 32 + nt * 8 + lc * 2;
            size_t i0 = (size_t)r0 * N + cc;
            size_t i1 = (size_t)(r0 + 8) * N + cc;
            if (mode == 0) {
                *(float2*)(C + i0) = make_float2(acc[mt][nt][0], acc[mt][nt][1]);
                *(float2*)(C + i1) = make_float2(acc[mt][nt][2], acc[mt][nt][3]);
            } else {
                float2 w0 = *(const float2*)(Wold + i0);
                float2 w1 = *(const float2*)(Wold + i1);
                w0.x += scale * acc[mt][nt][0]; w0.y += scale * acc[mt][nt][1];
                w1.x += scale * acc[mt][nt][2]; w1.y += scale * acc[mt][nt][3];
                *(float2*)(C + i0) = w0;
                *(float2*)(C + i1) = w1;
            }
        }
    }
}

// ---------------------------------------------------------------------------
// Prep kernels
// ---------------------------------------------------------------------------
__global__ void rna_kernel(const float* __restrict__ in, float* __restrict__ out, size_t n4) {
    size_t i = (size_t)blockIdx.x * blockDim.x + threadIdx.x;
    if (i < n4) {
        float4 v = ((const float4*)in)[i];
        v.x = rna_tf32(v.x); v.y = rna_tf32(v.y);
        v.z = rna_tf32(v.z); v.w = rna_tf32(v.w);
        ((float4*)out)[i] = v;
    }
}

// XT[i][b] = rna(X[b][i])
__global__ void xt_kernel(const float* __restrict__ X, float* __restrict__ XT,
                          int Bn, int INn) {
    __shared__ float t[32][33];
    int b0 = blockIdx.x * 32, i0 = blockIdx.y * 32;
    int tx = threadIdx.x, ty = threadIdx.y;
    for (int r = ty; r < 32; r += 8)
        t[r][tx] = X[(size_t)(b0 + r) * INn + i0 + tx];
    __syncthreads();
    for (int r = ty; r < 32; r += 8)
        XT[(size_t)(i0 + r) * Bn + b0 + tx] = rna_tf32(t[tx][r]);
}

// PT[o][b] = rna(max(O[b][o] - th[o], 0))
__global__ void pt_kernel(const float* __restrict__ O, const float* __restrict__ th,
                          float* __restrict__ PT, int Bn, int OUTn) {
    __shared__ float t[32][33];
    int b0 = blockIdx.x * 32, o0 = blockIdx.y * 32;
    int tx = threadIdx.x, ty = threadIdx.y;
    for (int r = ty; r < 32; r += 8)
        t[r][tx] = O[(size_t)(b0 + r) * OUTn + o0 + tx];
    __syncthreads();
    for (int r = ty; r < 32; r += 8) {
        float thv = __ldg(th + o0 + r);
        PT[(size_t)(o0 + r) * Bn + b0 + tx] = rna_tf32(fmaxf(t[tx][r] - thv, 0.f));
    }
}

__global__ void colsum_kernel(const float* __restrict__ Out, int Bn, int OUTn) {
    int col = blockIdx.x * blockDim.x + threadIdx.x;
    if (col >= OUTn) return;
    int rows_per = Bn / RSPLIT;
    int r0 = blockIdx.y * rows_per;
    float s = 0.f;
    for (int r = 0; r < rows_per; r++)
        s += Out[(size_t)(r0 + r) * OUTn + col];
    g_partial[blockIdx.y * OUTn + col] = s;
}

__global__ void thresh_kernel(const float* __restrict__ th_old,
                              float* __restrict__ th_new, int Bn, int OUTn) {
    int c = blockIdx.x * blockDim.x + threadIdx.x;
    if (c >= OUTn) return;
    float s = 0.f;
    #pragma unroll 8
    for (int p = 0; p < RSPLIT; p++) s += g_partial[p * OUTn + c];
    float act = s / (float)Bn;
    float t = th_old[c];
    th_new[c] = t + (act * act - t) / TAU_C;
}

// ---------------------------------------------------------------------------
extern "C" void kernel_launch(void* const* d_in, const int* in_sizes, int n_in,
                              void* d_out, int out_size)
{
    const float* x  = (const float*)d_in[0];
    const float* w  = (const float*)d_in[1];
    const float* th = (const float*)d_in[2];

    const int OUT = in_sizes[2];
    const int IN  = in_sizes[1] / OUT;
    const int Bn  = in_sizes[0] / IN;

    float* out    = (float*)d_out;
    float* out_O  = out;                          // B x OUT
    float* out_th = out + (size_t)Bn * OUT;       // OUT
    float* out_W  = out_th + OUT;                 // OUT x IN

    void *p;
    cudaGetSymbolAddress(&p, g_xr); float* XR = (float*)p;
    cudaGetSymbolAddress(&p, g_wr); float* WR = (float*)p;
    cudaGetSymbolAddress(&p, g_xt); float* XT = (float*)p;
    cudaGetSymbolAddress(&p, g_pt); float* PT = (float*)p;

    cudaFuncSetAttribute(gemm_mma_kernel,
                         cudaFuncAttributeMaxDynamicSharedMemorySize, SMEM_TOTAL);

    // Pre-round operands to tf32 (RNA: unbiased)
    size_t nX = (size_t)Bn * IN, nW = (size_t)OUT * IN;
    rna_kernel<<<(unsigned)((nX / 4 + 255) / 256), 256>>>(x, XR, nX / 4);
    rna_kernel<<<(unsigned)((nW / 4 + 255) / 256), 256>>>(w, WR, nW / 4);
    xt_kernel<<<dim3(Bn / 32, IN / 32), dim3(32, 8)>>>(x, XT, Bn, IN);

    // 1) O = X @ W^T   (M=B, N=OUT, K=IN)
    dim3 g1(OUT / BN, Bn / BM);
    gemm_mma_kernel<<<g1, 256, SMEM_TOTAL>>>(XR, WR, nullptr, out_O,
                                             Bn, OUT, IN, 0.f, 0);

    // 2) threshold EMA (deterministic two-stage reduction)
    dim3 gr((OUT + 255) / 256, RSPLIT);
    colsum_kernel<<<gr, 256>>>(out_O, Bn, OUT);
    thresh_kernel<<<(OUT + 255) / 256, 256>>>(th, out_th, Bn, OUT);

    // 3) PT = relu(O - th)^T ; Wnew = W + (LR/B) * PT @ XT^T  (M=OUT, N=IN, K=B)
    pt_kernel<<<dim3(Bn / 32, OUT / 32), dim3(32, 8)>>>(out_O, out_th, PT, Bn, OUT);
    dim3 g2(IN / BN, OUT / BM);
    gemm_mma_kernel<<<g2, 256, SMEM_TOTAL>>>(PT, XT, w, out_W,
                                             OUT, IN, Bn, LR_C / (float)Bn, 1);
}

// round 4
// speedup vs baseline: 5.0468x; 1.2573x over previous
#include <cuda_runtime.h>
#include <cstdint>
#include <cstddef>

#define LR_C   0.001f
#define TAU_C  1000.0f

// GEMM tiling
#define BM 128
#define BN 128
#define BKT 32
#define NSTAGES 3
#define STAGE_BYTES (2 * BM * 128)          // As 16KB + Bs 16KB
#define SMEM_TOTAL (NSTAGES * STAGE_BYTES)  // 96 KB
#define RSPLIT 64

// Fixed problem shape: B=8192, IN=OUT=4096.
#define DIM_B   8192
#define DIM_IO  4096

// Scratch (__device__ globals: the sanctioned alloc-free workaround)
__device__ float g_xr[(size_t)DIM_B * DIM_IO];   // rna(x)            B x IN
__device__ float g_wr[(size_t)DIM_IO * DIM_IO];  // rna(w)            OUT x IN
__device__ float g_xt[(size_t)DIM_IO * DIM_B];   // rna(x)^T          IN x B
__device__ float g_pt[(size_t)DIM_IO * DIM_B];   // rna(relu(o-th))^T OUT x B
__device__ float g_partial[RSPLIT * DIM_IO];

// ---------------------------------------------------------------------------
// PTX helpers (baseline sm_80+ features ONLY — no tcgen05 on this toolchain)
// ---------------------------------------------------------------------------
__device__ __forceinline__ uint32_t smem_u32(const void* p) {
    return (uint32_t)__cvta_generic_to_shared(p);
}

__device__ __forceinline__ float rna_tf32(float x) {
    uint32_t r;
    asm("cvt.rna.tf32.f32 %0, %1;" : "=r"(r) : "f"(x));
    return __uint_as_float(r);
}

__device__ __forceinline__ void cp_async16(uint32_t s, const void* g) {
    asm volatile("cp.async.cg.shared.global [%0], [%1], 16;\n" :: "r"(s), "l"(g));
}
#define CP_COMMIT() asm volatile("cp.async.commit_group;\n" ::)
#define CP_WAIT1()  asm volatile("cp.async.wait_group 1;\n" ::: "memory")

// ldmatrix x4 on 32-bit data: each 8x8-b16 matrix == 8x4-b32 tile; thread t
// gets (row t/4, b32-word t%4) of its matrix — exactly the tf32 frag layout.
__device__ __forceinline__ void ldsm_x4(uint32_t* r, uint32_t addr) {
    asm volatile("ldmatrix.sync.aligned.m8n8.x4.shared.b16 {%0,%1,%2,%3}, [%4];"
                 : "=r"(r[0]), "=r"(r[1]), "=r"(r[2]), "=r"(r[3]) : "r"(addr));
}

__device__ __forceinline__ uint32_t sw128(uint32_t off) {
    return off ^ ((off >> 3) & 0x70);
}

// m16n8k8 tf32 MMA, fp32 accumulate
__device__ __forceinline__ void mma_1688(float* c, const uint32_t* a,
                                         uint32_t b0, uint32_t b1) {
    asm volatile(
        "mma.sync.aligned.m16n8k8.row.col.f32.tf32.tf32.f32 "
        "{%0,%1,%2,%3}, {%4,%5,%6,%7}, {%8,%9}, {%0,%1,%2,%3};"
        : "+f"(c[0]), "+f"(c[1]), "+f"(c[2]), "+f"(c[3])
        : "r"(a[0]), "r"(a[1]), "r"(a[2]), "r"(a[3]), "r"(b0), "r"(b1));
}

// ---------------------------------------------------------------------------
// TF32 tensor-core GEMM: C[M,N] = A[M,K] * B[N,K]^T (both row-major / K-major)
// mode 0: C = D       mode 1: C = Wold + scale * D
// ---------------------------------------------------------------------------
__device__ __forceinline__ void load_stage(uint32_t smem_base, int stage,
                                           const float* Ab, const float* Bb,
                                           int K, int k0, int tid) {
    uint32_t sa = smem_base + stage * STAGE_BYTES;
    uint32_t sb = sa + BM * 128;
    #pragma unroll
    for (int i = 0; i < 4; i++) {            // A: 128 rows x 8 x 16B chunks
        int idx = tid + i * 256;
        int row = idx >> 3, c = idx & 7;
        cp_async16(sa + sw128((uint32_t)(row * 128 + c * 16)),
                   (const char*)(Ab + (size_t)row * K + k0) + c * 16);
    }
    #pragma unroll
    for (int i = 0; i < 4; i++) {            // B: 128 rows x 8 x 16B chunks
        int idx = tid + i * 256;
        int row = idx >> 3, c = idx & 7;
        cp_async16(sb + sw128((uint32_t)(row * 128 + c * 16)),
                   (const char*)(Bb + (size_t)row * K + k0) + c * 16);
    }
}

__global__ __launch_bounds__(256, 2) void gemm_mma_kernel(
    const float* __restrict__ A, const float* __restrict__ Bmat,
    const float* __restrict__ Wold, float* __restrict__ C,
    int M, int N, int K, float scale, int mode)
{
    extern __shared__ char smem[];
    const uint32_t smem_base = smem_u32(smem);
    const int tid  = threadIdx.x;
    const int warp = tid >> 5, lane = tid & 31;
    const int wm = warp >> 2, wn = warp & 3;       // 2 x 4 warp grid
    const int lr = lane >> 2, lc = lane & 3;

    const int mbase = blockIdx.y * BM;
    const int nbase = blockIdx.x * BN;
    const float* Ab = A + (size_t)mbase * K;
    const float* Bb = Bmat + (size_t)nbase * K;

    // ldmatrix per-thread addressing invariants (swizzle mask = (row&7)<<4,
    // and row&7 == lane&7 for every fragment row this thread addresses).
    const uint32_t swz_mask = (uint32_t)((lane & 7) << 4);
    // A: mat = lane/8: mat0 rows+0 k0-3 | mat1 rows+8 k0-3 | mat2 rows+0 k4-7 | mat3 rows+8 k4-7
    const int arow = wm * 64 + ((lane >> 3) & 1) * 8 + (lane & 7);
    const uint32_t a_kb = (uint32_t)((lane >> 4) * 16);         // k-half byte offset
    uint32_t a_rowoff[4];
    #pragma unroll
    for (int mt = 0; mt < 4; mt++) a_rowoff[mt] = (uint32_t)((arow + mt * 16) * 128);
    // B (x4 covers 2 n-tiles): mat0 n+0 k0-3 | mat1 n+0 k4-7 | mat2 n+8 k0-3 | mat3 n+8 k4-7
    const int brow = wn * 32 + ((lane >> 4) & 1) * 8 + (lane & 7);
    const uint32_t b_kb = (uint32_t)(((lane >> 3) & 1) * 16);
    uint32_t b_rowoff[2];
    #pragma unroll
    for (int p = 0; p < 2; p++) b_rowoff[p] = (uint32_t)((brow + p * 16) * 128);

    float acc[4][4][4];                            // [mt][nt][frag]
    #pragma unroll
    for (int i = 0; i < 4; i++)
        #pragma unroll
        for (int j = 0; j < 4; j++)
            #pragma unroll
            for (int f = 0; f < 4; f++) acc[i][j][f] = 0.f;

    const int niter = K / BKT;

    load_stage(smem_base, 0, Ab, Bb, K, 0, tid);   CP_COMMIT();
    load_stage(smem_base, 1, Ab, Bb, K, BKT, tid); CP_COMMIT();

    int buf = 0;
    for (int it = 0; it < niter; ++it) {
        CP_WAIT1();
        __syncthreads();
        uint32_t sa = smem_base + buf * STAGE_BYTES;
        uint32_t sb = sa + BM * 128;

        #pragma unroll
        for (int ks = 0; ks < BKT / 8; ks++) {
            const uint32_t xa = ((uint32_t)(ks * 32) + a_kb) ^ swz_mask;
            const uint32_t xb = ((uint32_t)(ks * 32) + b_kb) ^ swz_mask;
            uint32_t a[4][4], b[2][4];
            #pragma unroll
            for (int mt = 0; mt < 4; mt++) ldsm_x4(a[mt], sa + a_rowoff[mt] + xa);
            #pragma unroll
            for (int p = 0; p < 2; p++)    ldsm_x4(b[p], sb + b_rowoff[p] + xb);
            #pragma unroll
            for (int mt = 0; mt < 4; mt++) {
                #pragma unroll
                for (int p = 0; p < 2; p++) {
                    mma_1688(acc[mt][2 * p],     a[mt], b[p][0], b[p][1]);
                    mma_1688(acc[mt][2 * p + 1], a[mt], b[p][2], b[p][3]);
                }
            }
        }

        const int itn = it + 2;
        if (itn < niter)
            load_stage(smem_base, itn % NSTAGES, Ab, Bb, K, itn * BKT, tid);
        CP_COMMIT();
        buf = (buf + 1 == NSTAGES) ? 0 : buf + 1;
    }

    // Epilogue: per thread 4x4 tiles, two float2 rows each
    #pragma unroll
    for (int mt = 0; mt < 4; mt++) {
        int r0 = mbase + wm * 64 + mt * 16 + lr;
        #pragma unroll
        for (int nt = 0; nt < 4; nt++) {
            int cc = nbase + wn * 32 + nt * 8 + lc * 2;
            size_t i0 = (size_t)r0 * N + cc;
            size_t i1 = (size_t)(r0 + 8) * N + cc;
            if (mode == 0) {
                *(float2*)(C + i0) = make_float2(acc[mt][nt][0], acc[mt][nt][1]);
                *(float2*)(C + i1) = make_float2(acc[mt][nt][2], acc[mt][nt][3]);
            } else {
                float2 w0 = *(const float2*)(Wold + i0);
                float2 w1 = *(const float2*)(Wold + i1);
                w0.x += scale * acc[mt][nt][0]; w0.y += scale * acc[mt][nt][1];
                w1.x += scale * acc[mt][nt][2]; w1.y += scale * acc[mt][nt][3];
                *(float2*)(C + i0) = w0;
                *(float2*)(C + i1) = w1;
            }
        }
    }
}

// ---------------------------------------------------------------------------
// Prep kernels
// ---------------------------------------------------------------------------
__global__ void rna_kernel(const float* __restrict__ in, float* __restrict__ out, size_t n4) {
    size_t i = (size_t)blockIdx.x * blockDim.x + threadIdx.x;
    if (i < n4) {
        float4 v = ((const float4*)in)[i];
        v.x = rna_tf32(v.x); v.y = rna_tf32(v.y);
        v.z = rna_tf32(v.z); v.w = rna_tf32(v.w);
        ((float4*)out)[i] = v;
    }
}

// One pass over x: XR[b][i] = rna(x[b][i]); XT[i][b] = rna(x[b][i])
__global__ void prep_x_kernel(const float* __restrict__ X, float* __restrict__ XR,
                              float* __restrict__ XT, int Bn, int INn) {
    __shared__ float t[32][33];
    int b0 = blockIdx.x * 32, i0 = blockIdx.y * 32;
    int tx = threadIdx.x, ty = threadIdx.y;
    for (int r = ty; r < 32; r += 8) {
        float v = rna_tf32(X[(size_t)(b0 + r) * INn + i0 + tx]);
        t[r][tx] = v;
        XR[(size_t)(b0 + r) * INn + i0 + tx] = v;
    }
    __syncthreads();
    for (int r = ty; r < 32; r += 8)
        XT[(size_t)(i0 + r) * Bn + b0 + tx] = t[tx][r];
}

// PT[o][b] = rna(max(O[b][o] - th[o], 0))
__global__ void pt_kernel(const float* __restrict__ O, const float* __restrict__ th,
                          float* __restrict__ PT, int Bn, int OUTn) {
    __shared__ float t[32][33];
    int b0 = blockIdx.x * 32, o0 = blockIdx.y * 32;
    int tx = threadIdx.x, ty = threadIdx.y;
    for (int r = ty; r < 32; r += 8)
        t[r][tx] = O[(size_t)(b0 + r) * OUTn + o0 + tx];
    __syncthreads();
    for (int r = ty; r < 32; r += 8) {
        float thv = __ldg(th + o0 + r);
        PT[(size_t)(o0 + r) * Bn + b0 + tx] = rna_tf32(fmaxf(t[tx][r] - thv, 0.f));
    }
}

__global__ void colsum_kernel(const float* __restrict__ Out, int Bn, int OUTn) {
    int col = blockIdx.x * blockDim.x + threadIdx.x;
    if (col >= OUTn) return;
    int rows_per = Bn / RSPLIT;
    int r0 = blockIdx.y * rows_per;
    float s = 0.f;
    for (int r = 0; r < rows_per; r++)
        s += Out[(size_t)(r0 + r) * OUTn + col];
    g_partial[blockIdx.y * OUTn + col] = s;
}

__global__ void thresh_kernel(const float* __restrict__ th_old,
                              float* __restrict__ th_new, int Bn, int OUTn) {
    int c = blockIdx.x * blockDim.x + threadIdx.x;
    if (c >= OUTn) return;
    float s = 0.f;
    #pragma unroll 8
    for (int p = 0; p < RSPLIT; p++) s += g_partial[p * OUTn + c];
    float act = s / (float)Bn;
    float t = th_old[c];
    th_new[c] = t + (act * act - t) / TAU_C;
}

// ---------------------------------------------------------------------------
extern "C" void kernel_launch(void* const* d_in, const int* in_sizes, int n_in,
                              void* d_out, int out_size)
{
    const float* x  = (const float*)d_in[0];
    const float* w  = (const float*)d_in[1];
    const float* th = (const float*)d_in[2];

    const int OUT = in_sizes[2];
    const int IN  = in_sizes[1] / OUT;
    const int Bn  = in_sizes[0] / IN;

    float* out    = (float*)d_out;
    float* out_O  = out;                          // B x OUT
    float* out_th = out + (size_t)Bn * OUT;       // OUT
    float* out_W  = out_th + OUT;                 // OUT x IN

    void *p;
    cudaGetSymbolAddress(&p, g_xr); float* XR = (float*)p;
    cudaGetSymbolAddress(&p, g_wr); float* WR = (float*)p;
    cudaGetSymbolAddress(&p, g_xt); float* XT = (float*)p;
    cudaGetSymbolAddress(&p, g_pt); float* PT = (float*)p;

    cudaFuncSetAttribute(gemm_mma_kernel,
                         cudaFuncAttributeMaxDynamicSharedMemorySize, SMEM_TOTAL);

    // Pre-round operands to tf32 (RNA: unbiased)
    size_t nW = (size_t)OUT * IN;
    prep_x_kernel<<<dim3(Bn / 32, IN / 32), dim3(32, 8)>>>(x, XR, XT, Bn, IN);
    rna_kernel<<<(unsigned)((nW / 4 + 255) / 256), 256>>>(w, WR, nW / 4);

    // 1) O = X @ W^T   (M=B, N=OUT, K=IN)
    dim3 g1(OUT / BN, Bn / BM);
    gemm_mma_kernel<<<g1, 256, SMEM_TOTAL>>>(XR, WR, nullptr, out_O,
                                             Bn, OUT, IN, 0.f, 0);

    // 2) threshold EMA (deterministic two-stage reduction)
    dim3 gr((OUT + 255) / 256, RSPLIT);
    colsum_kernel<<<gr, 256>>>(out_O, Bn, OUT);
    thresh_kernel<<<(OUT + 255) / 256, 256>>>(th, out_th, Bn, OUT);

    // 3) PT = relu(O - th)^T ; Wnew = W + (LR/B) * PT @ XT^T  (M=OUT, N=IN, K=B)
    pt_kernel<<<dim3(Bn / 32, OUT / 32), dim3(32, 8)>>>(out_O, out_th, PT, Bn, OUT);
    dim3 g2(IN / BN, OUT / BM);
    gemm_mma_kernel<<<g2, 256, SMEM_TOTAL>>>(PT, XT, w, out_W,
                                             OUT, IN, Bn, LR_C / (float)Bn, 1);
}